// round 7
// baseline (speedup 1.0000x reference)
#include <cuda_runtime.h>

// filtfilt (5-tap butter-style IIR, odd ext padlen=15) over 512 rows, T=32768.
//
// R6: span-dedup. A warp's 32 chunks tile the row contiguously; their load
// window union (incl. WARM=64 warm-up) is ONE contiguous span of 2144 floats.
// Load it once (sequential coalesced, 1.03x amplification vs 1.97x for
// per-chunk tiles), compute from smem with lane stride CH=65 (== 1 mod 32,
// conflict-free), and route only emitted samples through a 32x33 transpose
// tile for coalesced global stores.
// Stable filter (max |pole|=0.80): WARM=64 -> state error 0.8^64 ~ 6e-7.
// The reference's per-row scale/descale is a linear no-op and skipped.

#define T_LEN     32768
#define PAD       15
#define TEXT      (T_LEN + 2 * PAD)   // 32798
#define ROWSTRIDE 32800
#define MAXROWS   512
#define NCH       512                 // chunks per row
#define CH        65                  // NCH*CH = 33280 >= TEXT; CH % 32 == 1
#define WARM      64
#define WIN       (WARM + CH)         // 129
#define WPB       4                   // warps per block
#define BLOCK     (WPB * 32)          // 128
#define BPR       (NCH / (WPB * 32))  // blocks per row = 4
#define SPAN      (WARM + 32 * CH)    // 2144 floats (67 * 32)
#define TILE_F    (32 * 33)
#define SMEM_BYTES ((WPB * (SPAN + TILE_F)) * 4)   // 51200 B

__device__ float g_fwd[(size_t)MAXROWS * ROWSTRIDE];

struct Coef {
    float b0, b1, b2, b3, b4;
    float na1, na2, na3, na4;
};

__device__ __forceinline__ Coef load_coef(const float* __restrict__ bc,
                                          const float* __restrict__ ac) {
    Coef c;
    float inva0 = 1.0f / ac[0];
    c.b0 = bc[0] * inva0; c.b1 = bc[1] * inva0; c.b2 = bc[2] * inva0;
    c.b3 = bc[3] * inva0; c.b4 = bc[4] * inva0;
    c.na1 = -ac[1] * inva0; c.na2 = -ac[2] * inva0;
    c.na3 = -ac[3] * inva0; c.na4 = -ac[4] * inva0;
    return c;
}

// Direct-Form-I step; critical chain is the final fma through y1 (4 cyc).
#define IIR_STEP(xt)                                                   \
    do {                                                               \
        float f = fmaf(c.b0, (xt), fmaf(c.b1, x1,                      \
                  fmaf(c.b2, x2, fmaf(c.b3, x3, c.b4 * x4))));         \
        float s_ = fmaf(c.na2, y2, fmaf(c.na3, y3,                     \
                   fmaf(c.na4, y4, f)));                               \
        float y = fmaf(c.na1, y1, s_);                                 \
        x4 = x3; x3 = x2; x2 = x1; x1 = (xt);                          \
        y4 = y3; y3 = y2; y2 = y1; y1 = y;                             \
    } while (0)

// Odd-extended input at extended index t; 0 outside [0, TEXT).
__device__ __forceinline__ float load_xe_safe(const float* __restrict__ xr, int t) {
    if (t < 0)            return 0.0f;
    if (t < PAD)          return 2.0f * xr[0]         - xr[PAD - t];
    if (t < T_LEN + PAD)  return xr[t - PAD];
    if (t < TEXT)         return 2.0f * xr[T_LEN - 1] - xr[2 * T_LEN + PAD - 2 - t];
    return 0.0f;
}

__global__ void __launch_bounds__(BLOCK)
fwd_kernel(const float* __restrict__ x,
           const float* __restrict__ bc,
           const float* __restrict__ ac) {
    extern __shared__ float dyn[];
    int wir  = threadIdx.x >> 5;
    int lane = threadIdx.x & 31;
    float* span = dyn + wir * SPAN;
    float (*tile)[33] = (float (*)[33])(dyn + WPB * SPAN + wir * TILE_F);

    int row  = blockIdx.x / BPR;
    int part = blockIdx.x - row * BPR;
    int c0   = part * (WPB * 32) + wir * 32;   // first chunk of this warp
    int sb   = c0 * CH - WARM;                 // span start (extended index)
    bool fast = (c0 != 0) && (c0 + 32 != NCH); // span fully inside [0, TEXT)

    Coef c = load_coef(bc, ac);
    const float* xr = x + (size_t)row * T_LEN;
    float*       yr = g_fwd + (size_t)row * ROWSTRIDE;

    // Phase 1: contiguous coalesced span load (67 rounds, exact).
    if (fast) {
        const float* p = xr + (sb - PAD);
        #pragma unroll 8
        for (int u = lane; u < SPAN; u += 32) span[u] = p[u];
    } else {
        for (int u = lane; u < SPAN; u += 32) span[u] = load_xe_safe(xr, sb + u);
    }
    __syncwarp();

    // Phase 2/3: lane l runs chunk c0+l from span[l*CH .. l*CH+WIN).
    const float* ps = span + lane * CH;        // lane stride 65: conflict-free
    float x1 = 0.f, x2 = 0.f, x3 = 0.f, x4 = 0.f;
    float y1 = 0.f, y2 = 0.f, y3 = 0.f, y4 = 0.f;

    // Warm-up (j = 0..63), 8-batched loads, no emission.
    for (int jb = 0; jb < WARM; jb += 8) {
        float v[8];
        #pragma unroll
        for (int k = 0; k < 8; ++k) v[k] = ps[jb + k];
        #pragma unroll
        for (int k = 0; k < 8; ++k) IIR_STEP(v[k]);
    }
    // Emit groups of 32 (j = 64..95, 96..127) via transpose tile.
    for (int g = 0; g < 2; ++g) {
        for (int kb = 0; kb < 32; kb += 8) {
            float v[8];
            #pragma unroll
            for (int k = 0; k < 8; ++k) v[k] = ps[WARM + g * 32 + kb + k];
            #pragma unroll
            for (int k = 0; k < 8; ++k) { IIR_STEP(v[k]); tile[lane][kb + k] = y1; }
        }
        __syncwarp();
        if (fast) {
            #pragma unroll 8
            for (int i = 0; i < 32; ++i)
                yr[sb + i * CH + WARM + g * 32 + lane] = tile[i][lane];
        } else {
            #pragma unroll 4
            for (int i = 0; i < 32; ++i) {
                int t = sb + i * CH + WARM + g * 32 + lane;
                if (t >= 0 && t < TEXT) yr[t] = tile[i][lane];
            }
        }
        __syncwarp();
    }
    // Leftover sample j = 128 (one per chunk; strided store, negligible).
    {
        float v = ps[WARM + 64];
        IIR_STEP(v);
        int t = sb + lane * CH + WARM + 64;
        if (t < TEXT) yr[t] = y1;
    }
}

__global__ void __launch_bounds__(BLOCK)
bwd_kernel(const float* __restrict__ bc,
           const float* __restrict__ ac,
           float* __restrict__ out) {
    extern __shared__ float dyn[];
    int wir  = threadIdx.x >> 5;
    int lane = threadIdx.x & 31;
    float* span = dyn + wir * SPAN;
    float (*tile)[33] = (float (*)[33])(dyn + WPB * SPAN + wir * TILE_F);

    int row  = blockIdx.x / BPR;
    int part = blockIdx.x - row * BPR;
    int c0   = part * (WPB * 32) + wir * 32;
    int sb   = c0 * CH - WARM;                 // reversed-index span start
    bool fast = (c0 != 0) && (c0 + 32 != NCH);

    Coef c = load_coef(bc, ac);
    const float* yr   = g_fwd + (size_t)row * ROWSTRIDE;
    float*       orow = out   + (size_t)row * T_LEN;

    // Phase 1: span of the time-reversed forward result: u -> yr[TEXT-1-(sb+u)]
    // (descending-consecutive global addresses: still fully coalesced).
    if (fast) {
        const float* p = yr + (TEXT - 1 - sb);
        #pragma unroll 8
        for (int u = lane; u < SPAN; u += 32) span[u] = p[-u];
    } else {
        for (int u = lane; u < SPAN; u += 32) {
            int s = sb + u;
            span[u] = (s >= 0 && s < TEXT) ? yr[TEXT - 1 - s] : 0.f;
        }
    }
    __syncwarp();

    const float* ps = span + lane * CH;
    float x1 = 0.f, x2 = 0.f, x3 = 0.f, x4 = 0.f;
    float y1 = 0.f, y2 = 0.f, y3 = 0.f, y4 = 0.f;

    for (int jb = 0; jb < WARM; jb += 8) {
        float v[8];
        #pragma unroll
        for (int k = 0; k < 8; ++k) v[k] = ps[jb + k];
        #pragma unroll
        for (int k = 0; k < 8; ++k) IIR_STEP(v[k]);
    }
    // Emit: reversed position s = sb + i*CH + j; output index
    // (TEXT-1-PAD) - s, valid for s in [PAD, TEXT-1-PAD].
    for (int g = 0; g < 2; ++g) {
        for (int kb = 0; kb < 32; kb += 8) {
            float v[8];
            #pragma unroll
            for (int k = 0; k < 8; ++k) v[k] = ps[WARM + g * 32 + kb + k];
            #pragma unroll
            for (int k = 0; k < 8; ++k) { IIR_STEP(v[k]); tile[lane][kb + k] = y1; }
        }
        __syncwarp();
        if (fast) {
            float* q = orow + (TEXT - 1 - PAD) - (sb + WARM + g * 32 + lane);
            #pragma unroll 8
            for (int i = 0; i < 32; ++i) q[-i * CH] = tile[i][lane];
        } else {
            #pragma unroll 4
            for (int i = 0; i < 32; ++i) {
                int s = sb + i * CH + WARM + g * 32 + lane;
                if (s >= PAD && s <= TEXT - 1 - PAD)
                    orow[(TEXT - 1 - PAD) - s] = tile[i][lane];
            }
        }
        __syncwarp();
    }
    {
        float v = ps[WARM + 64];
        IIR_STEP(v);
        int s = sb + lane * CH + WARM + 64;
        if (s >= PAD && s <= TEXT - 1 - PAD)
            orow[(TEXT - 1 - PAD) - s] = y1;
    }
}

extern "C" void kernel_launch(void* const* d_in, const int* in_sizes, int n_in,
                              void* d_out, int out_size) {
    const float* x  = (const float*)d_in[0];
    const float* bc = (const float*)d_in[1];
    const float* ac = (const float*)d_in[2];
    float* out = (float*)d_out;

    int nrows  = in_sizes[0] / T_LEN;   // 512
    int blocks = nrows * BPR;           // 2048

    static int configured = 0;
    if (!configured) {
        cudaFuncSetAttribute(fwd_kernel,
                             cudaFuncAttributeMaxDynamicSharedMemorySize,
                             SMEM_BYTES);
        cudaFuncSetAttribute(bwd_kernel,
                             cudaFuncAttributeMaxDynamicSharedMemorySize,
                             SMEM_BYTES);
        configured = 1;
    }

    fwd_kernel<<<blocks, BLOCK, SMEM_BYTES>>>(x, bc, ac);
    bwd_kernel<<<blocks, BLOCK, SMEM_BYTES>>>(bc, ac, out);
}

// round 8
// speedup vs baseline: 1.1889x; 1.1889x over previous
#include <cuda_runtime.h>

// filtfilt (5-tap butter-style IIR, odd ext padlen=15) over 512 rows, T=32768.
//
// R7: tile architecture of R5 (best so far: bwd 45.9us @ occ 49%) with the
// warm-up shortened 63->48 and CH raised 65->80: work amplification
// (WARM+CH)/CH drops 1.97 -> 1.60, cutting FMA, smem and redundant-read
// traffic ~19% in BOTH passes at unchanged occupancy. Error budget: measured
// rel_err ~ 1.6*0.8^WARM (max |pole| = 0.80); 0.8^48 -> ~3.5e-5, 28x under
// the 1e-3 gate. NCH=416 chunks of CH=80 per row; 13 warps/row packed into
// 256-thread blocks via global warp id.
// Reference's per-row scale/descale is a linear no-op, skipped.

#define T_LEN     32768
#define PAD       15
#define TEXT      (T_LEN + 2 * PAD)   // 32798
#define ROWSTRIDE 32800
#define MAXROWS   512
#define NCH       416                 // chunks per row (13 * 32)
#define CH        80                  // NCH*CH = 33280 >= TEXT
#define WARM      48
#define WIN       (WARM + CH)         // 128
#define TILES     (WIN / 32)          // 4
#define WPR       13                  // warps per row
#define WPB       8                   // warps per block
#define BLOCK     (WPB * 32)          // 256

__device__ float g_fwd[(size_t)MAXROWS * ROWSTRIDE];

struct Coef {
    float b0, b1, b2, b3, b4;
    float na1, na2, na3, na4;
};

__device__ __forceinline__ Coef load_coef(const float* __restrict__ bc,
                                          const float* __restrict__ ac) {
    Coef c;
    float inva0 = 1.0f / ac[0];
    c.b0 = bc[0] * inva0; c.b1 = bc[1] * inva0; c.b2 = bc[2] * inva0;
    c.b3 = bc[3] * inva0; c.b4 = bc[4] * inva0;
    c.na1 = -ac[1] * inva0; c.na2 = -ac[2] * inva0;
    c.na3 = -ac[3] * inva0; c.na4 = -ac[4] * inva0;
    return c;
}

// Direct-Form-I step; critical chain is the final fma through y1 (4 cyc).
#define IIR_STEP(xt)                                                   \
    do {                                                               \
        float f = fmaf(c.b0, (xt), fmaf(c.b1, x1,                      \
                  fmaf(c.b2, x2, fmaf(c.b3, x3, c.b4 * x4))));         \
        float s_ = fmaf(c.na2, y2, fmaf(c.na3, y3,                     \
                   fmaf(c.na4, y4, f)));                               \
        float y = fmaf(c.na1, y1, s_);                                 \
        x4 = x3; x3 = x2; x2 = x1; x1 = (xt);                          \
        y4 = y3; y3 = y2; y2 = y1; y1 = y;                             \
    } while (0)

__device__ __forceinline__ float load_xe_safe(const float* __restrict__ xr, int t) {
    if (t < 0)            return 0.0f;
    if (t < PAD)          return 2.0f * xr[0]         - xr[PAD - t];
    if (t < T_LEN + PAD)  return xr[t - PAD];
    if (t < TEXT)         return 2.0f * xr[T_LEN - 1] - xr[2 * T_LEN + PAD - 2 - t];
    return 0.0f;
}

__device__ __forceinline__ float load_rev_safe(const float* __restrict__ yr, int s) {
    if (s < 0 || s >= TEXT) return 0.0f;
    return yr[TEXT - 1 - s];
}

__global__ void __launch_bounds__(BLOCK)
fwd_kernel(const float* __restrict__ x,
           const float* __restrict__ bc,
           const float* __restrict__ ac) {
    int wib  = threadIdx.x >> 5;
    int lane = threadIdx.x & 31;
    int gw   = blockIdx.x * WPB + wib;
    int row  = gw / WPR;
    int wir  = gw - row * WPR;

    Coef c = load_coef(bc, ac);
    const float* xr = x + (size_t)row * T_LEN;
    float*       yr = g_fwd + (size_t)row * ROWSTRIDE;

    __shared__ float tile_s[WPB][32][33];
    float (*sm)[33] = tile_s[wib];

    int c0   = wir * 32;               // first chunk of this warp
    int base = c0 * CH - WARM;
    bool fast = (c0 != 0) && (c0 != NCH - 32);

    float x1 = 0.f, x2 = 0.f, x3 = 0.f, x4 = 0.f;
    float y1 = 0.f, y2 = 0.f, y3 = 0.f, y4 = 0.f;

    #pragma unroll
    for (int tl = 0; tl < TILES; ++tl) {
        int off = tl * 32;
        // Phase 1: coalesced transposed loads (tile[i][*] = chunk c0+i).
        if (fast) {
            const float* p = xr + (base - PAD) + off + lane;
            #pragma unroll 8
            for (int i = 0; i < 32; ++i) sm[i][lane] = p[i * CH];
        } else {
            #pragma unroll 4
            for (int i = 0; i < 32; ++i)
                sm[i][lane] = load_xe_safe(xr, base + i * CH + off + lane);
        }
        __syncwarp();
        // Phase 2: lane advances its chunk 32 steps (8-batched LDS).
        #pragma unroll
        for (int jb = 0; jb < 32; jb += 8) {
            float v[8];
            #pragma unroll
            for (int k = 0; k < 8; ++k) v[k] = sm[lane][jb + k];
            #pragma unroll
            for (int k = 0; k < 8; ++k) {
                IIR_STEP(v[k]);
                sm[lane][jb + k] = y1;
            }
        }
        __syncwarp();
        // Phase 3: coalesced stores of emitted samples (off+lane >= WARM).
        if (tl >= 2) {
            if (fast) {
                float* q = yr + base + off + lane;
                #pragma unroll 8
                for (int i = 0; i < 32; ++i) q[i * CH] = sm[i][lane];
            } else {
                #pragma unroll 4
                for (int i = 0; i < 32; ++i) {
                    int t = base + i * CH + off + lane;
                    if (t >= 0 && t < TEXT) yr[t] = sm[i][lane];
                }
            }
        } else if (tl == 1) {
            if (lane >= WARM - 32) {       // lanes 16..31 (off+lane >= 48)
                if (fast) {
                    float* q = yr + base + off + lane;
                    #pragma unroll 8
                    for (int i = 0; i < 32; ++i) q[i * CH] = sm[i][lane];
                } else {
                    #pragma unroll 4
                    for (int i = 0; i < 32; ++i) {
                        int t = base + i * CH + off + lane;
                        if (t >= 0 && t < TEXT) yr[t] = sm[i][lane];
                    }
                }
            }
        }
        __syncwarp();
    }
}

__global__ void __launch_bounds__(BLOCK)
bwd_kernel(const float* __restrict__ bc,
           const float* __restrict__ ac,
           float* __restrict__ out) {
    int wib  = threadIdx.x >> 5;
    int lane = threadIdx.x & 31;
    int gw   = blockIdx.x * WPB + wib;
    int row  = gw / WPR;
    int wir  = gw - row * WPR;

    Coef c = load_coef(bc, ac);
    const float* yr   = g_fwd + (size_t)row * ROWSTRIDE;
    float*       orow = out   + (size_t)row * T_LEN;

    __shared__ float tile_s[WPB][32][33];
    float (*sm)[33] = tile_s[wib];

    int c0   = wir * 32;
    int base = c0 * CH - WARM;
    bool fast = (c0 != 0) && (c0 != NCH - 32);

    float x1 = 0.f, x2 = 0.f, x3 = 0.f, x4 = 0.f;
    float y1 = 0.f, y2 = 0.f, y3 = 0.f, y4 = 0.f;

    #pragma unroll
    for (int tl = 0; tl < TILES; ++tl) {
        int off = tl * 32;
        // Phase 1: reversed-time reads (descending-consecutive, coalesced).
        if (fast) {
            const float* p = yr + (TEXT - 1) - (base + off + lane);
            #pragma unroll 8
            for (int i = 0; i < 32; ++i) sm[i][lane] = p[-i * CH];
        } else {
            #pragma unroll 4
            for (int i = 0; i < 32; ++i)
                sm[i][lane] = load_rev_safe(yr, base + i * CH + off + lane);
        }
        __syncwarp();
        #pragma unroll
        for (int jb = 0; jb < 32; jb += 8) {
            float v[8];
            #pragma unroll
            for (int k = 0; k < 8; ++k) v[k] = sm[lane][jb + k];
            #pragma unroll
            for (int k = 0; k < 8; ++k) {
                IIR_STEP(v[k]);
                sm[lane][jb + k] = y1;
            }
        }
        __syncwarp();
        // Phase 3: out position t = TEXT-1-s in crop [PAD, T+PAD)
        // -> s in [PAD, TEXT-1-PAD]; out idx (TEXT-1-PAD) - s, coalesced.
        if (tl >= 2) {
            if (fast) {
                float* q = orow + (TEXT - 1 - PAD) - (base + off + lane);
                #pragma unroll 8
                for (int i = 0; i < 32; ++i) q[-i * CH] = sm[i][lane];
            } else {
                #pragma unroll 4
                for (int i = 0; i < 32; ++i) {
                    int s = base + i * CH + off + lane;
                    if (s >= PAD && s <= TEXT - 1 - PAD)
                        orow[(TEXT - 1 - PAD) - s] = sm[i][lane];
                }
            }
        } else if (tl == 1) {
            if (lane >= WARM - 32) {       // lanes 16..31
                if (fast) {
                    float* q = orow + (TEXT - 1 - PAD) - (base + off + lane);
                    #pragma unroll 8
                    for (int i = 0; i < 32; ++i) q[-i * CH] = sm[i][lane];
                } else {
                    #pragma unroll 4
                    for (int i = 0; i < 32; ++i) {
                        int s = base + i * CH + off + lane;
                        if (s >= PAD && s <= TEXT - 1 - PAD)
                            orow[(TEXT - 1 - PAD) - s] = sm[i][lane];
                    }
                }
            }
        }
        __syncwarp();
    }
}

extern "C" void kernel_launch(void* const* d_in, const int* in_sizes, int n_in,
                              void* d_out, int out_size) {
    const float* x  = (const float*)d_in[0];
    const float* bc = (const float*)d_in[1];
    const float* ac = (const float*)d_in[2];
    float* out = (float*)d_out;

    int nrows  = in_sizes[0] / T_LEN;          // 512
    int total_warps = nrows * WPR;             // 6656
    int blocks = total_warps / WPB;            // 832 (exact)

    fwd_kernel<<<blocks, BLOCK>>>(x, bc, ac);
    bwd_kernel<<<blocks, BLOCK>>>(bc, ac, out);
}

// round 9
// speedup vs baseline: 1.2590x; 1.0590x over previous
#include <cuda_runtime.h>

// filtfilt (5-tap butter-style IIR, odd ext padlen=15) over 512 rows, T=32768.
//
// R9 = R7 (WARM=48, CH=80, NCH=416, tile pipeline) + instruction-stream diet:
//  - phase-2 smem traffic via LDS.128/STS.128 (tile stride 36 floats keeps
//    16B alignment; <=4-way bank conflicts absorbed by the 4-phase minimum),
//  - fwd phase-3 via LDS.128 + STG.128 (ascending stores are 16B-aligned:
//    base = c0*80-48 = 0 mod 4, off in {64,96}),
//  - bwd keeps scalar descending loads/stores (parity-misaligned for vectors),
//  - WPB=4 (128-thread blocks, 18KB smem) for higher residency.
// Stable filter (max |pole|=0.80), WARM=48: measured rel_err ~4e-6.
// Reference's per-row scale/descale is a linear no-op, skipped.

#define T_LEN     32768
#define PAD       15
#define TEXT      (T_LEN + 2 * PAD)   // 32798
#define ROWSTRIDE 32800
#define MAXROWS   512
#define NCH       416                 // chunks per row (13 * 32)
#define CH        80                  // NCH*CH = 33280 >= TEXT
#define WARM      48
#define WIN       (WARM + CH)         // 128
#define TILES     (WIN / 32)          // 4
#define WPR       13                  // warps per row
#define WPB       4                   // warps per block
#define BLOCK     (WPB * 32)          // 128
#define TW        36                  // tile row stride (floats), 16B-multiple

#define LD128(p)    (*reinterpret_cast<const float4*>(p))
#define ST128(p, v) (*reinterpret_cast<float4*>(p) = (v))

__device__ float g_fwd[(size_t)MAXROWS * ROWSTRIDE];

struct Coef {
    float b0, b1, b2, b3, b4;
    float na1, na2, na3, na4;
};

__device__ __forceinline__ Coef load_coef(const float* __restrict__ bc,
                                          const float* __restrict__ ac) {
    Coef c;
    float inva0 = 1.0f / ac[0];
    c.b0 = bc[0] * inva0; c.b1 = bc[1] * inva0; c.b2 = bc[2] * inva0;
    c.b3 = bc[3] * inva0; c.b4 = bc[4] * inva0;
    c.na1 = -ac[1] * inva0; c.na2 = -ac[2] * inva0;
    c.na3 = -ac[3] * inva0; c.na4 = -ac[4] * inva0;
    return c;
}

// Direct-Form-I step; critical chain is the final fma through y1 (4 cyc).
#define IIR_STEP(xt)                                                   \
    do {                                                               \
        float f = fmaf(c.b0, (xt), fmaf(c.b1, x1,                      \
                  fmaf(c.b2, x2, fmaf(c.b3, x3, c.b4 * x4))));         \
        float s_ = fmaf(c.na2, y2, fmaf(c.na3, y3,                     \
                   fmaf(c.na4, y4, f)));                               \
        float y = fmaf(c.na1, y1, s_);                                 \
        x4 = x3; x3 = x2; x2 = x1; x1 = (xt);                          \
        y4 = y3; y3 = y2; y2 = y1; y1 = y;                             \
    } while (0)

// 8 IIR steps on a loaded octet, writing results back (emit tiles only).
#define P2_OCTET(jb, do_store)                                         \
    do {                                                               \
        float4 va = LD128(&sm[lane][jb]);                              \
        float4 vb = LD128(&sm[lane][(jb) + 4]);                        \
        float4 wa, wb;                                                 \
        IIR_STEP(va.x); wa.x = y1; IIR_STEP(va.y); wa.y = y1;          \
        IIR_STEP(va.z); wa.z = y1; IIR_STEP(va.w); wa.w = y1;          \
        IIR_STEP(vb.x); wb.x = y1; IIR_STEP(vb.y); wb.y = y1;          \
        IIR_STEP(vb.z); wb.z = y1; IIR_STEP(vb.w); wb.w = y1;          \
        if (do_store) {                                                \
            ST128(&sm[lane][jb], wa);                                  \
            ST128(&sm[lane][(jb) + 4], wb);                            \
        }                                                              \
    } while (0)

__device__ __forceinline__ float load_xe_safe(const float* __restrict__ xr, int t) {
    if (t < 0)            return 0.0f;
    if (t < PAD)          return 2.0f * xr[0]         - xr[PAD - t];
    if (t < T_LEN + PAD)  return xr[t - PAD];
    if (t < TEXT)         return 2.0f * xr[T_LEN - 1] - xr[2 * T_LEN + PAD - 2 - t];
    return 0.0f;
}

__device__ __forceinline__ float load_rev_safe(const float* __restrict__ yr, int s) {
    if (s < 0 || s >= TEXT) return 0.0f;
    return yr[TEXT - 1 - s];
}

__global__ void __launch_bounds__(BLOCK)
fwd_kernel(const float* __restrict__ x,
           const float* __restrict__ bc,
           const float* __restrict__ ac) {
    int wib  = threadIdx.x >> 5;
    int lane = threadIdx.x & 31;
    int gw   = blockIdx.x * WPB + wib;
    int row  = gw / WPR;
    int wir  = gw - row * WPR;

    Coef c = load_coef(bc, ac);
    const float* xr = x + (size_t)row * T_LEN;
    float*       yr = g_fwd + (size_t)row * ROWSTRIDE;

    __shared__ float tile_s[WPB][32][TW];
    float (*sm)[TW] = tile_s[wib];

    int c0   = wir * 32;
    int base = c0 * CH - WARM;
    bool fast = (wir != 0) && (wir != WPR - 1);

    float x1 = 0.f, x2 = 0.f, x3 = 0.f, x4 = 0.f;
    float y1 = 0.f, y2 = 0.f, y3 = 0.f, y4 = 0.f;

    #pragma unroll
    for (int tl = 0; tl < TILES; ++tl) {
        int off = tl * 32;
        // Phase 1: coalesced transposed loads (sm[i][*] = chunk c0+i).
        if (fast) {
            const float* p = xr + (base - PAD) + off + lane;
            #pragma unroll 8
            for (int i = 0; i < 32; ++i) sm[i][lane] = p[i * CH];
        } else {
            #pragma unroll 4
            for (int i = 0; i < 32; ++i)
                sm[i][lane] = load_xe_safe(xr, base + i * CH + off + lane);
        }
        __syncwarp();
        // Phase 2: 32 IIR steps via 128-bit smem ops.
        P2_OCTET(0,  tl >= 2);
        P2_OCTET(8,  tl >= 2);
        P2_OCTET(16, tl >= 1);
        P2_OCTET(24, tl >= 1);
        __syncwarp();
        // Phase 3: emitted-sample stores.
        if (tl >= 2) {
            if (fast) {
                int i0 = lane >> 3, q4 = (lane & 7) * 4;
                #pragma unroll
                for (int r8 = 0; r8 < 8; ++r8) {
                    int i = r8 * 4 + i0;
                    float4 v = LD128(&sm[i][q4]);
                    ST128(yr + base + i * CH + off + q4, v);
                }
            } else {
                #pragma unroll 4
                for (int i = 0; i < 32; ++i) {
                    int t = base + i * CH + off + lane;
                    if (t >= 0 && t < TEXT) yr[t] = sm[i][lane];
                }
            }
        } else if (tl == 1) {
            if (lane >= 16) {            // off+lane >= 48 == WARM
                if (fast) {
                    float* q = yr + base + off + lane;
                    #pragma unroll 8
                    for (int i = 0; i < 32; ++i) q[i * CH] = sm[i][lane];
                } else {
                    #pragma unroll 4
                    for (int i = 0; i < 32; ++i) {
                        int t = base + i * CH + off + lane;
                        if (t >= 0 && t < TEXT) yr[t] = sm[i][lane];
                    }
                }
            }
        }
        __syncwarp();
    }
}

__global__ void __launch_bounds__(BLOCK)
bwd_kernel(const float* __restrict__ bc,
           const float* __restrict__ ac,
           float* __restrict__ out) {
    int wib  = threadIdx.x >> 5;
    int lane = threadIdx.x & 31;
    int gw   = blockIdx.x * WPB + wib;
    int row  = gw / WPR;
    int wir  = gw - row * WPR;

    Coef c = load_coef(bc, ac);
    const float* yr   = g_fwd + (size_t)row * ROWSTRIDE;
    float*       orow = out   + (size_t)row * T_LEN;

    __shared__ float tile_s[WPB][32][TW];
    float (*sm)[TW] = tile_s[wib];

    int c0   = wir * 32;
    int base = c0 * CH - WARM;
    bool fast = (wir != 0) && (wir != WPR - 1);

    float x1 = 0.f, x2 = 0.f, x3 = 0.f, x4 = 0.f;
    float y1 = 0.f, y2 = 0.f, y3 = 0.f, y4 = 0.f;

    #pragma unroll
    for (int tl = 0; tl < TILES; ++tl) {
        int off = tl * 32;
        // Phase 1: reversed-time reads (descending-consecutive, coalesced).
        if (fast) {
            const float* p = yr + (TEXT - 1) - (base + off + lane);
            #pragma unroll 8
            for (int i = 0; i < 32; ++i) sm[i][lane] = p[-i * CH];
        } else {
            #pragma unroll 4
            for (int i = 0; i < 32; ++i)
                sm[i][lane] = load_rev_safe(yr, base + i * CH + off + lane);
        }
        __syncwarp();
        P2_OCTET(0,  tl >= 2);
        P2_OCTET(8,  tl >= 2);
        P2_OCTET(16, tl >= 1);
        P2_OCTET(24, tl >= 1);
        __syncwarp();
        // Phase 3: out position t = TEXT-1-s in crop [PAD, T+PAD)
        // -> s in [PAD, TEXT-1-PAD]; out idx (TEXT-1-PAD) - s (descending).
        if (tl >= 2) {
            if (fast) {
                float* q = orow + (TEXT - 1 - PAD) - (base + off + lane);
                #pragma unroll 8
                for (int i = 0; i < 32; ++i) q[-i * CH] = sm[i][lane];
            } else {
                #pragma unroll 4
                for (int i = 0; i < 32; ++i) {
                    int s = base + i * CH + off + lane;
                    if (s >= PAD && s <= TEXT - 1 - PAD)
                        orow[(TEXT - 1 - PAD) - s] = sm[i][lane];
                }
            }
        } else if (tl == 1) {
            if (lane >= 16) {
                if (fast) {
                    float* q = orow + (TEXT - 1 - PAD) - (base + off + lane);
                    #pragma unroll 8
                    for (int i = 0; i < 32; ++i) q[-i * CH] = sm[i][lane];
                } else {
                    #pragma unroll 4
                    for (int i = 0; i < 32; ++i) {
                        int s = base + i * CH + off + lane;
                        if (s >= PAD && s <= TEXT - 1 - PAD)
                            orow[(TEXT - 1 - PAD) - s] = sm[i][lane];
                    }
                }
            }
        }
        __syncwarp();
    }
}

extern "C" void kernel_launch(void* const* d_in, const int* in_sizes, int n_in,
                              void* d_out, int out_size) {
    const float* x  = (const float*)d_in[0];
    const float* bc = (const float*)d_in[1];
    const float* ac = (const float*)d_in[2];
    float* out = (float*)d_out;

    int nrows  = in_sizes[0] / T_LEN;          // 512
    int total_warps = nrows * WPR;             // 6656
    int blocks = total_warps / WPB;            // 1664 (exact)

    fwd_kernel<<<blocks, BLOCK>>>(x, bc, ac);
    bwd_kernel<<<blocks, BLOCK>>>(bc, ac, out);
}